// round 6
// baseline (speedup 1.0000x reference)
#include <cuda_runtime.h>
#include <cuda_fp16.h>

#define NN 50000
#define EE 1600000
#define SCB 196              // ceil(NN/256) scan blocks
#define GEMM_BLKS 148
#define EDGE_BLKS 148

// ---- scratch ----
__device__ uint2  g_xp2[NN * 32];        // node projections fp16 [N,128]
__device__ float  g_as[NN * 4];
__device__ float  g_at[NN * 4];
__device__ uint2  g_aeh[EE];             // per-edge a_e, 4 halfs
__device__ uint4  g_rec[EE];             // CSR: {w01h2, w23h2, src, pad}
__device__ int    g_deg[NN];
__device__ int    g_off[NN + 1];
__device__ int    g_cur[NN];
__device__ int    g_bsum[SCB];
__device__ float  g_ve[64];

__device__ __forceinline__ unsigned long long pack2f(float a, float b) {
    unsigned long long r;
    asm("mov.b64 %0, {%1, %2};" : "=l"(r) : "f"(a), "f"(b));
    return r;
}
__device__ __forceinline__ void unpack2f(unsigned long long v, float& a, float& b) {
    asm("mov.b64 {%0, %1}, %2;" : "=f"(a), "=f"(b) : "l"(v));
}
__device__ __forceinline__ unsigned long long fma2f(unsigned long long a,
                                                    unsigned long long b,
                                                    unsigned long long c) {
    unsigned long long r;
    asm("fma.rn.f32x2 %0, %1, %2, %3;" : "=l"(r) : "l"(a), "l"(b), "l"(c));
    return r;
}

// ---------------------------------------------------------------
// K0: zero degree histogram + fold W_edge with w_e
__global__ void k_init(const float* __restrict__ W_edge,
                       const float* __restrict__ w_e) {
    int i = blockIdx.x * blockDim.x + threadIdx.x;
    if (i < NN) g_deg[i] = 0;
    if (blockIdx.x == 0 && threadIdx.x < 64) {
        int h = threadIdx.x >> 4, k = threadIdx.x & 15;
        float s = 0.f;
#pragma unroll
        for (int f = 0; f < 32; f++) s += w_e[f] * W_edge[(h * 32 + f) * 16 + k];
        g_ve[threadIdx.x] = s;
    }
}

// ---------------------------------------------------------------
// K1: grid=296 (2 blocks/SM). bid<148: persistent GEMM block.
//     bid>=148: persistent edge block (degree histogram + a_e dot).
__global__ __launch_bounds__(256, 2) void k_node(
    const float* __restrict__ x, const int* __restrict__ ei,
    const float* __restrict__ ea,
    const float* __restrict__ W_lin, const float* __restrict__ W_res,
    const float* __restrict__ bias,
    const float* __restrict__ w_s, const float* __restrict__ b_s,
    const float* __restrict__ w_t, const float* __restrict__ b_t,
    float* __restrict__ out) {
    int t = threadIdx.x;
    if (blockIdx.x >= GEMM_BLKS) {
        __shared__ float sve[64];
        if (t < 64) sve[t] = g_ve[t];
        __syncthreads();
        for (int e = (blockIdx.x - GEMM_BLKS) * 256 + t; e < EE;
             e += EDGE_BLKS * 256) {
            int dst = ei[EE + e];
            atomicAdd(&g_deg[dst], 1);
            const float4* p = (const float4*)ea + e * 4;
            float av[16];
#pragma unroll
            for (int i = 0; i < 4; i++) {
                float4 q = p[i];
                av[4 * i] = q.x; av[4 * i + 1] = q.y;
                av[4 * i + 2] = q.z; av[4 * i + 3] = q.w;
            }
            float r[4];
#pragma unroll
            for (int h = 0; h < 4; h++) {
                const float* vv = sve + h * 16;
                float s = 0.f;
#pragma unroll
                for (int k = 0; k < 16; k++) s += vv[k] * av[k];
                r[h] = s;
            }
            half2 r01 = __floats2half2_rn(r[0], r[1]);
            half2 r23 = __floats2half2_rn(r[2], r[3]);
            uint2 u;
            u.x = *(unsigned*)&r01;
            u.y = *(unsigned*)&r23;
            g_aeh[e] = u;
        }
        return;
    }
    // ---- GEMM path ----
    __shared__ float sx[16 * 64];
    __shared__ float sxp[16 * 132];
    __shared__ float sws[32], swt[32];

    unsigned long long w2[32];
    {
        const float4* Wrow = (t < 128) ? ((const float4*)W_lin + t * 16)
                                       : ((const float4*)W_res + (t - 128) * 16);
#pragma unroll
        for (int k = 0; k < 16; k++) {
            float4 v = Wrow[k];
            w2[2 * k]     = pack2f(v.x, v.y);
            w2[2 * k + 1] = pack2f(v.z, v.w);
        }
    }
    float bval = (t >= 128) ? bias[t - 128] : 0.f;
    if (t < 32) sws[t] = w_s[t];
    else if (t < 64) swt[t - 32] = w_t[t - 32];
    float bsv = b_s[0], btv = b_t[0];
    int th = t >> 5, tf = t & 31;

    for (int tile = blockIdx.x; tile < NN / 16; tile += GEMM_BLKS) {
        int n0 = tile * 16;
        __syncthreads();
        ((float4*)sx)[(t >> 4) * 16 + (t & 15)] =
            ((const float4*)x)[(n0 + (t >> 4)) * 16 + (t & 15)];
        __syncthreads();
#pragma unroll 1
        for (int i = 0; i < 16; i++) {
            const ulonglong2* xr = (const ulonglong2*)(sx + i * 64);
            unsigned long long a0 = 0ull, a1 = 0ull;
#pragma unroll
            for (int k = 0; k < 16; k++) {
                ulonglong2 xv = xr[k];
                a0 = fma2f(w2[2 * k],     xv.x, a0);
                a1 = fma2f(w2[2 * k + 1], xv.y, a1);
            }
            float l0, h0, l1, h1;
            unpack2f(a0, l0, h0);
            unpack2f(a1, l1, h1);
            float acc = (l0 + l1) + (h0 + h1);
            if (t < 128) {
                sxp[i * 132 + th * 33 + tf] = acc;
                ((__half*)g_xp2)[(n0 + i) * 128 + t] = __float2half(acc);
            } else {
                out[(n0 + i) * 128 + (t - 128)] = acc + bval;
            }
        }
        __syncthreads();
        if (t < 128) {
            int i = t >> 3, task = t & 7, h = task & 3;
            const float* wv  = (task < 4) ? sws : swt;
            const float* xpr = sxp + i * 132 + h * 33;
            float s = 0.f;
#pragma unroll
            for (int f = 0; f < 32; f++) s += xpr[f] * wv[f];
            if (task < 4) g_as[(n0 + i) * 4 + h] = s + bsv;
            else          g_at[(n0 + i) * 4 + h] = s + btv;
        }
    }
}

// ---------------------------------------------------------------
__global__ __launch_bounds__(256) void k_scan1() {
    __shared__ int s[8];
    int t = threadIdx.x;
    int idx = blockIdx.x * 256 + t;
    int v = (idx < NN) ? g_deg[idx] : 0;
#pragma unroll
    for (int o = 16; o > 0; o >>= 1) v += __shfl_down_sync(0xffffffffu, v, o);
    if ((t & 31) == 0) s[t >> 5] = v;
    __syncthreads();
    if (t == 0) {
        int sum = 0;
#pragma unroll
        for (int i = 0; i < 8; i++) sum += s[i];
        g_bsum[blockIdx.x] = sum;
    }
}

__global__ __launch_bounds__(256) void k_scan2() {
    __shared__ int s[256];
    int t = threadIdx.x;
    int v = (t < SCB) ? g_bsum[t] : 0;
    s[t] = v;
    __syncthreads();
#pragma unroll
    for (int d = 1; d < 256; d <<= 1) {
        int u = (t >= d) ? s[t - d] : 0;
        __syncthreads();
        s[t] += u;
        __syncthreads();
    }
    if (t < SCB) g_bsum[t] = s[t] - v;
}

__global__ __launch_bounds__(256) void k_scan3() {
    __shared__ int s[256];
    int t = threadIdx.x;
    int idx = blockIdx.x * 256 + t;
    int d = (idx < NN) ? g_deg[idx] : 0;
    s[t] = d;
    __syncthreads();
#pragma unroll
    for (int dd = 1; dd < 256; dd <<= 1) {
        int u = (t >= dd) ? s[t - dd] : 0;
        __syncthreads();
        s[t] += u;
        __syncthreads();
    }
    int base = g_bsum[blockIdx.x];
    if (idx < NN) {
        int off = base + s[t] - d;
        g_off[idx] = off;
        g_cur[idx] = off;
        if (idx == NN - 1) g_off[NN] = off + d;
    }
}

// ---------------------------------------------------------------
// K4: scatter pass — 4 coalesced streams/thread.
__global__ __launch_bounds__(256) void k_scatter(
    const int* __restrict__ ei, const float* __restrict__ b_e) {
    const int QU = EE / 4;
    int gid = blockIdx.x * blockDim.x + threadIdx.x;
    if (gid >= QU) return;
    float bev = b_e[0];

    int   e[4], src[4], dst[4];
    uint2 ae[4];
    float4 as4[4], at4[4];
#pragma unroll
    for (int k = 0; k < 4; k++) e[k] = gid + k * QU;
#pragma unroll
    for (int k = 0; k < 4; k++) { src[k] = ei[e[k]]; dst[k] = ei[EE + e[k]]; }
#pragma unroll
    for (int k = 0; k < 4; k++) ae[k] = g_aeh[e[k]];
#pragma unroll
    for (int k = 0; k < 4; k++) {
        as4[k] = ((const float4*)g_as)[src[k]];
        at4[k] = ((const float4*)g_at)[dst[k]];
    }
#pragma unroll
    for (int k = 0; k < 4; k++) {
        float2 a01 = __half22float2(*(half2*)&ae[k].x);
        float2 a23 = __half22float2(*(half2*)&ae[k].y);
        float al[4];
        al[0] = a01.x + as4[k].x + at4[k].x + bev;
        al[1] = a01.y + as4[k].y + at4[k].y + bev;
        al[2] = a23.x + as4[k].z + at4[k].z + bev;
        al[3] = a23.y + as4[k].w + at4[k].w + bev;
        float w[4];
#pragma unroll
        for (int h = 0; h < 4; h++) {
            float s = (al[h] >= 0.f) ? al[h] : 0.2f * al[h];
            w[h] = __expf(s);
        }
        int pos = atomicAdd(&g_cur[dst[k]], 1);
        half2 w01 = __floats2half2_rn(w[0], w[1]);
        half2 w23 = __floats2half2_rn(w[2], w[3]);
        uint4 rec;
        rec.x = *(unsigned*)&w01;
        rec.y = *(unsigned*)&w23;
        rec.z = (unsigned)src[k];
        rec.w = 0u;
        g_rec[pos] = rec;
    }
}

// ---------------------------------------------------------------
// K5: TWO warps per destination node, smem combine.
// FIX vs r5: softmax denominator sw is PER-LANE (per-head) data -> store
// the full 32-lane sw vector (ssw[4][32]), not just lane 0's value.
__global__ __launch_bounds__(256) void k_aggr(float* __restrict__ out) {
    __shared__ float4 sacc[4][32];
    __shared__ float  ssw[4][32];
    int wid  = threadIdx.x >> 5;
    int lane = threadIdx.x & 31;
    int nl   = wid >> 1;               // node slot in block (0..3)
    int half = wid & 1;
    int n = blockIdx.x * 4 + nl;
    int h = lane >> 3;

    int beg = g_off[n], end = g_off[n + 1];
    int mid = beg + ((end - beg) >> 1);
    int p  = half ? mid : beg;
    int pe = half ? end : mid;

    float4 acc = make_float4(0.f, 0.f, 0.f, 0.f);
    float sw = 0.f;
    for (; p + 8 <= pe; p += 8) {
        uint4 r[8];
#pragma unroll
        for (int j = 0; j < 8; j++) r[j] = g_rec[p + j];
        uint2 xv[8];
#pragma unroll
        for (int j = 0; j < 8; j++) xv[j] = g_xp2[r[j].z * 32 + lane];
#pragma unroll
        for (int j = 0; j < 8; j++) {
            unsigned wp = (h & 2) ? r[j].y : r[j].x;
            half2 hw = *(half2*)&wp;
            float w = (h & 1) ? __high2float(hw) : __low2float(hw);
            float2 fa = __half22float2(*(const half2*)&xv[j].x);
            float2 fb = __half22float2(*(const half2*)&xv[j].y);
            acc.x += w * fa.x; acc.y += w * fa.y;
            acc.z += w * fb.x; acc.w += w * fb.y;
            sw += w;
        }
    }
    if (p + 4 <= pe) {
        uint4 r[4];
#pragma unroll
        for (int j = 0; j < 4; j++) r[j] = g_rec[p + j];
        uint2 xv[4];
#pragma unroll
        for (int j = 0; j < 4; j++) xv[j] = g_xp2[r[j].z * 32 + lane];
#pragma unroll
        for (int j = 0; j < 4; j++) {
            unsigned wp = (h & 2) ? r[j].y : r[j].x;
            half2 hw = *(half2*)&wp;
            float w = (h & 1) ? __high2float(hw) : __low2float(hw);
            float2 fa = __half22float2(*(const half2*)&xv[j].x);
            float2 fb = __half22float2(*(const half2*)&xv[j].y);
            acc.x += w * fa.x; acc.y += w * fa.y;
            acc.z += w * fb.x; acc.w += w * fb.y;
            sw += w;
        }
        p += 4;
    }
    for (; p < pe; p++) {
        uint4 r = g_rec[p];
        unsigned wp = (h & 2) ? r.y : r.x;
        half2 hw = *(half2*)&wp;
        float w = (h & 1) ? __high2float(hw) : __low2float(hw);
        uint2 xv = g_xp2[r.z * 32 + lane];
        float2 fa = __half22float2(*(const half2*)&xv.x);
        float2 fb = __half22float2(*(const half2*)&xv.y);
        acc.x += w * fa.x; acc.y += w * fa.y;
        acc.z += w * fb.x; acc.w += w * fb.y;
        sw += w;
    }
    if (half) {
        sacc[nl][lane] = acc;
        ssw[nl][lane] = sw;
    }
    __syncthreads();
    if (!half) {
        float4 o = sacc[nl][lane];
        acc.x += o.x; acc.y += o.y; acc.z += o.z; acc.w += o.w;
        sw += ssw[nl][lane];
        float inv = (sw > 0.f) ? (1.f / sw) : 0.f;
        float4* o4 = (float4*)out + n * 32 + lane;
        float4 ov = *o4;                 // residual + bias from K1
        ov.x += inv * acc.x; ov.y += inv * acc.y;
        ov.z += inv * acc.z; ov.w += inv * acc.w;
        *o4 = ov;
    }
}

// ---------------------------------------------------------------
extern "C" void kernel_launch(void* const* d_in, const int* in_sizes, int n_in,
                              void* d_out, int out_size) {
    const float* x      = (const float*)d_in[0];
    const int*   ei     = (const int*)  d_in[1];
    const float* ea     = (const float*)d_in[2];
    const float* W_lin  = (const float*)d_in[3];
    const float* w_s    = (const float*)d_in[4];
    const float* b_s    = (const float*)d_in[5];
    const float* w_t    = (const float*)d_in[6];
    const float* b_t    = (const float*)d_in[7];
    const float* W_edge = (const float*)d_in[8];
    const float* w_e    = (const float*)d_in[9];
    const float* b_e    = (const float*)d_in[10];
    const float* W_res  = (const float*)d_in[11];
    const float* bias   = (const float*)d_in[12];
    float* out = (float*)d_out;

    k_init<<<(NN + 255) / 256, 256>>>(W_edge, w_e);
    k_node<<<GEMM_BLKS + EDGE_BLKS, 256>>>(x, ei, ea, W_lin, W_res, bias,
                                           w_s, b_s, w_t, b_t, out);
    k_scan1<<<SCB, 256>>>();
    k_scan2<<<1, 256>>>();
    k_scan3<<<SCB, 256>>>();
    k_scatter<<<(EE / 4 + 255) / 256, 256>>>(ei, b_e);
    k_aggr<<<NN / 4, 256>>>(out);
}

// round 7
// speedup vs baseline: 1.0368x; 1.0368x over previous
#include <cuda_runtime.h>
#include <cuda_fp16.h>

#define NN 50000
#define EE 1600000
#define SCB 196          // ceil(NN/256) scan blocks
#define NODE_BLKS 600
#define DEG_BLKS  1024

// ---- scratch ----
__device__ uint2  g_xp2[NN * 32];        // node projections fp16 [N,128]
__device__ float  g_as[NN * 4];
__device__ float  g_at[NN * 4];
__device__ uint2  g_aeh[EE];             // per-edge a_e, 4 halfs
__device__ uint4  g_rec[EE];             // CSR: {w01h2, w23h2, src, pad}
__device__ int    g_deg[NN];
__device__ int    g_off[NN + 1];
__device__ int    g_cur[NN];
__device__ int    g_bsum[SCB];
__device__ float  g_ve[64];

__device__ __forceinline__ unsigned long long pack2f(float a, float b) {
    unsigned long long r;
    asm("mov.b64 %0, {%1, %2};" : "=l"(r) : "f"(a), "f"(b));
    return r;
}
__device__ __forceinline__ void unpack2f(unsigned long long v, float& a, float& b) {
    asm("mov.b64 {%0, %1}, %2;" : "=f"(a), "=f"(b) : "l"(v));
}
__device__ __forceinline__ unsigned long long fma2f(unsigned long long a,
                                                    unsigned long long b,
                                                    unsigned long long c) {
    unsigned long long r;
    asm("fma.rn.f32x2 %0, %1, %2, %3;" : "=l"(r) : "l"(a), "l"(b), "l"(c));
    return r;
}

// ---------------------------------------------------------------
// K0: zero degree histogram + fold W_edge with w_e
__global__ void k_init(const float* __restrict__ W_edge,
                       const float* __restrict__ w_e) {
    int i = blockIdx.x * blockDim.x + threadIdx.x;
    if (i < NN) g_deg[i] = 0;
    if (blockIdx.x == 0 && threadIdx.x < 64) {
        int h = threadIdx.x >> 4, k = threadIdx.x & 15;
        float s = 0.f;
#pragma unroll
        for (int f = 0; f < 32; f++) s += w_e[f] * W_edge[(h * 32 + f) * 16 + k];
        g_ve[threadIdx.x] = s;
    }
}

// ---------------------------------------------------------------
// K1: FUSED. blocks < NODE_BLKS: persistent GEMM (4/SM residency, barriers
//     hidden by co-resident GEMM blocks). Remaining DEG_BLKS blocks:
//     grid-stride edge pass (dst-degree histogram + a_e dot -> fp16),
//     memory work that hides under the compute-bound GEMM wave.
__global__ __launch_bounds__(256) void k_node(
    const float* __restrict__ x, const int* __restrict__ ei,
    const float* __restrict__ ea,
    const float* __restrict__ W_lin, const float* __restrict__ W_res,
    const float* __restrict__ bias,
    const float* __restrict__ w_s, const float* __restrict__ b_s,
    const float* __restrict__ w_t, const float* __restrict__ b_t,
    float* __restrict__ out) {
    int t = threadIdx.x;
    if (blockIdx.x >= NODE_BLKS) {
        // ---- edge pass: degree histogram + a_e dot ----
        __shared__ float sve[64];
        if (t < 64) sve[t] = g_ve[t];
        __syncthreads();
        int nb = gridDim.x - NODE_BLKS;
        for (int e = (blockIdx.x - NODE_BLKS) * 256 + t; e < EE;
             e += nb * 256) {
            int dst = ei[EE + e];
            atomicAdd(&g_deg[dst], 1);
            const float4* p = (const float4*)ea + e * 4;
            float av[16];
#pragma unroll
            for (int i = 0; i < 4; i++) {
                float4 q = p[i];
                av[4 * i] = q.x; av[4 * i + 1] = q.y;
                av[4 * i + 2] = q.z; av[4 * i + 3] = q.w;
            }
            float r[4];
#pragma unroll
            for (int h = 0; h < 4; h++) {
                const float* vv = sve + h * 16;
                float s = 0.f;
#pragma unroll
                for (int k = 0; k < 16; k++) s += vv[k] * av[k];
                r[h] = s;
            }
            half2 r01 = __floats2half2_rn(r[0], r[1]);
            half2 r23 = __floats2half2_rn(r[2], r[3]);
            uint2 u;
            u.x = *(unsigned*)&r01;
            u.y = *(unsigned*)&r23;
            g_aeh[e] = u;
        }
        return;
    }
    // ---- GEMM path ----
    __shared__ float sx[16 * 64];
    __shared__ float sxp[16 * 132];
    __shared__ float sws[32], swt[32];

    unsigned long long w2[32];
    {
        const float4* Wrow = (t < 128) ? ((const float4*)W_lin + t * 16)
                                       : ((const float4*)W_res + (t - 128) * 16);
#pragma unroll
        for (int k = 0; k < 16; k++) {
            float4 v = Wrow[k];
            w2[2 * k]     = pack2f(v.x, v.y);
            w2[2 * k + 1] = pack2f(v.z, v.w);
        }
    }
    float bval = (t >= 128) ? bias[t - 128] : 0.f;
    if (t < 32) sws[t] = w_s[t];
    else if (t < 64) swt[t - 32] = w_t[t - 32];
    float bsv = b_s[0], btv = b_t[0];
    int th = t >> 5, tf = t & 31;

    for (int tile = blockIdx.x; tile < NN / 16; tile += NODE_BLKS) {
        int n0 = tile * 16;
        __syncthreads();
        ((float4*)sx)[(t >> 4) * 16 + (t & 15)] =
            ((const float4*)x)[(n0 + (t >> 4)) * 16 + (t & 15)];
        __syncthreads();
#pragma unroll 1
        for (int i = 0; i < 16; i++) {
            const ulonglong2* xr = (const ulonglong2*)(sx + i * 64);
            unsigned long long a0 = 0ull, a1 = 0ull;
#pragma unroll
            for (int k = 0; k < 16; k++) {
                ulonglong2 xv = xr[k];
                a0 = fma2f(w2[2 * k],     xv.x, a0);
                a1 = fma2f(w2[2 * k + 1], xv.y, a1);
            }
            float l0, h0, l1, h1;
            unpack2f(a0, l0, h0);
            unpack2f(a1, l1, h1);
            float acc = (l0 + l1) + (h0 + h1);
            if (t < 128) {
                sxp[i * 132 + th * 33 + tf] = acc;
                ((__half*)g_xp2)[(n0 + i) * 128 + t] = __float2half(acc);
            } else {
                out[(n0 + i) * 128 + (t - 128)] = acc + bval;
            }
        }
        __syncthreads();
        if (t < 128) {
            int i = t >> 3, task = t & 7, h = task & 3;
            const float* wv  = (task < 4) ? sws : swt;
            const float* xpr = sxp + i * 132 + h * 33;
            float s = 0.f;
#pragma unroll
            for (int f = 0; f < 32; f++) s += xpr[f] * wv[f];
            if (task < 4) g_as[(n0 + i) * 4 + h] = s + bsv;
            else          g_at[(n0 + i) * 4 + h] = s + btv;
        }
    }
}

// ---------------------------------------------------------------
// K3a: per-block degree sums
__global__ __launch_bounds__(256) void k_scan1() {
    __shared__ int s[8];
    int t = threadIdx.x;
    int idx = blockIdx.x * 256 + t;
    int v = (idx < NN) ? g_deg[idx] : 0;
#pragma unroll
    for (int o = 16; o > 0; o >>= 1) v += __shfl_down_sync(0xffffffffu, v, o);
    if ((t & 31) == 0) s[t >> 5] = v;
    __syncthreads();
    if (t == 0) {
        int sum = 0;
#pragma unroll
        for (int i = 0; i < 8; i++) sum += s[i];
        g_bsum[blockIdx.x] = sum;
    }
}

// K3b: exclusive scan of block sums
__global__ __launch_bounds__(256) void k_scan2() {
    __shared__ int s[256];
    int t = threadIdx.x;
    int v = (t < SCB) ? g_bsum[t] : 0;
    s[t] = v;
    __syncthreads();
#pragma unroll
    for (int d = 1; d < 256; d <<= 1) {
        int u = (t >= d) ? s[t - d] : 0;
        __syncthreads();
        s[t] += u;
        __syncthreads();
    }
    if (t < SCB) g_bsum[t] = s[t] - v;
}

// K3c: local scan + base -> offsets & cursors
__global__ __launch_bounds__(256) void k_scan3() {
    __shared__ int s[256];
    int t = threadIdx.x;
    int idx = blockIdx.x * 256 + t;
    int d = (idx < NN) ? g_deg[idx] : 0;
    s[t] = d;
    __syncthreads();
#pragma unroll
    for (int dd = 1; dd < 256; dd <<= 1) {
        int u = (t >= dd) ? s[t - dd] : 0;
        __syncthreads();
        s[t] += u;
        __syncthreads();
    }
    int base = g_bsum[blockIdx.x];
    if (idx < NN) {
        int off = base + s[t] - d;
        g_off[idx] = off;
        g_cur[idx] = off;
        if (idx == NN - 1) g_off[NN] = off + d;
    }
}

// ---------------------------------------------------------------
// K4: LEAN scatter — reads precomputed fp16 a_e (8B/edge) instead of the
//     102MB edge_attr stream. 4 coalesced streams/thread for MLP.
__global__ __launch_bounds__(256) void k_scatter(
    const int* __restrict__ ei, const float* __restrict__ b_e) {
    const int QU = EE / 4;
    int gid = blockIdx.x * blockDim.x + threadIdx.x;
    if (gid >= QU) return;
    float bev = b_e[0];

    int   e[4], src[4], dst[4];
    uint2 ae[4];
    float4 as4[4], at4[4];
#pragma unroll
    for (int k = 0; k < 4; k++) e[k] = gid + k * QU;
#pragma unroll
    for (int k = 0; k < 4; k++) { src[k] = ei[e[k]]; dst[k] = ei[EE + e[k]]; }
#pragma unroll
    for (int k = 0; k < 4; k++) ae[k] = g_aeh[e[k]];
#pragma unroll
    for (int k = 0; k < 4; k++) {
        as4[k] = ((const float4*)g_as)[src[k]];
        at4[k] = ((const float4*)g_at)[dst[k]];
    }
#pragma unroll
    for (int k = 0; k < 4; k++) {
        float2 a01 = __half22float2(*(half2*)&ae[k].x);
        float2 a23 = __half22float2(*(half2*)&ae[k].y);
        float al[4];
        al[0] = a01.x + as4[k].x + at4[k].x + bev;
        al[1] = a01.y + as4[k].y + at4[k].y + bev;
        al[2] = a23.x + as4[k].z + at4[k].z + bev;
        al[3] = a23.y + as4[k].w + at4[k].w + bev;
        float w[4];
#pragma unroll
        for (int h = 0; h < 4; h++) {
            float s = (al[h] >= 0.f) ? al[h] : 0.2f * al[h];
            w[h] = __expf(s);
        }
        int pos = atomicAdd(&g_cur[dst[k]], 1);
        half2 w01 = __floats2half2_rn(w[0], w[1]);
        half2 w23 = __floats2half2_rn(w[2], w[3]);
        uint4 rec;
        rec.x = *(unsigned*)&w01;
        rec.y = *(unsigned*)&w23;
        rec.z = (unsigned)src[k];
        rec.w = 0u;
        g_rec[pos] = rec;
    }
}

// ---------------------------------------------------------------
// K5: ONE warp per destination node (r4 config — no inter-node coupling);
//     chunk-8 batched loads for MLP.
__global__ __launch_bounds__(256) void k_aggr(float* __restrict__ out) {
    int wid = (blockIdx.x * blockDim.x + threadIdx.x) >> 5;
    if (wid >= NN) return;
    int lane = threadIdx.x & 31;
    int h = lane >> 3;
    int beg = g_off[wid], end = g_off[wid + 1];

    float4 acc = make_float4(0.f, 0.f, 0.f, 0.f);
    float sw = 0.f;
    int p = beg;
    for (; p + 8 <= end; p += 8) {
        uint4 r[8];
#pragma unroll
        for (int j = 0; j < 8; j++) r[j] = g_rec[p + j];   // broadcast loads
        uint2 xv[8];
#pragma unroll
        for (int j = 0; j < 8; j++) xv[j] = g_xp2[r[j].z * 32 + lane];
#pragma unroll
        for (int j = 0; j < 8; j++) {
            unsigned wp = (h & 2) ? r[j].y : r[j].x;
            half2 hw = *(half2*)&wp;
            float w = (h & 1) ? __high2float(hw) : __low2float(hw);
            float2 fa = __half22float2(*(const half2*)&xv[j].x);
            float2 fb = __half22float2(*(const half2*)&xv[j].y);
            acc.x += w * fa.x; acc.y += w * fa.y;
            acc.z += w * fb.x; acc.w += w * fb.y;
            sw += w;
        }
    }
    for (; p < end; p++) {
        uint4 r = g_rec[p];
        unsigned wp = (h & 2) ? r.y : r.x;
        half2 hw = *(half2*)&wp;
        float w = (h & 1) ? __high2float(hw) : __low2float(hw);
        uint2 xv = g_xp2[r.z * 32 + lane];
        float2 fa = __half22float2(*(const half2*)&xv.x);
        float2 fb = __half22float2(*(const half2*)&xv.y);
        acc.x += w * fa.x; acc.y += w * fa.y;
        acc.z += w * fb.x; acc.w += w * fb.y;
        sw += w;
    }
    float inv = (sw > 0.f) ? (1.f / sw) : 0.f;
    float4* o4 = (float4*)out + wid * 32 + lane;
    float4 ov = *o4;
    ov.x += inv * acc.x; ov.y += inv * acc.y;
    ov.z += inv * acc.z; ov.w += inv * acc.w;
    *o4 = ov;
}

// ---------------------------------------------------------------
extern "C" void kernel_launch(void* const* d_in, const int* in_sizes, int n_in,
                              void* d_out, int out_size) {
    const float* x      = (const float*)d_in[0];
    const int*   ei     = (const int*)  d_in[1];
    const float* ea     = (const float*)d_in[2];
    const float* W_lin  = (const float*)d_in[3];
    const float* w_s    = (const float*)d_in[4];
    const float* b_s    = (const float*)d_in[5];
    const float* w_t    = (const float*)d_in[6];
    const float* b_t    = (const float*)d_in[7];
    const float* W_edge = (const float*)d_in[8];
    const float* w_e    = (const float*)d_in[9];
    const float* b_e    = (const float*)d_in[10];
    const float* W_res  = (const float*)d_in[11];
    const float* bias   = (const float*)d_in[12];
    float* out = (float*)d_out;

    k_init<<<(NN + 255) / 256, 256>>>(W_edge, w_e);
    k_node<<<NODE_BLKS + DEG_BLKS, 256>>>(x, ei, ea, W_lin, W_res, bias,
                                          w_s, b_s, w_t, b_t, out);
    k_scan1<<<SCB, 256>>>();
    k_scan2<<<1, 256>>>();
    k_scan3<<<SCB, 256>>>();
    k_scatter<<<(EE / 4 + 255) / 256, 256>>>(ei, b_e);
    k_aggr<<<(NN * 32) / 256, 256>>>(out);
}